// round 1
// baseline (speedup 1.0000x reference)
#include <cuda_runtime.h>
#include <cuda_bf16.h>

// Problem constants
#define CUR   512
#define HID   64
#define OUTD  64
#define HEADS 6
#define FTOT  (HEADS*OUTD)   // 384
#define CATD  (HID + FTOT)   // 448
#define NMAX  50000

// ---------------- device scratch (no allocations allowed) ----------------
__device__ float g_h[(size_t)NMAX * HID];        // 12.8 MB
__device__ float g_xh[(size_t)NMAX * FTOT];      // 76.8 MB
__device__ float g_asrc[(size_t)NMAX * HEADS];
__device__ float g_adst[(size_t)NMAX * HEADS];
__device__ float g_segmax[(size_t)NMAX * HEADS];
__device__ float g_denom[(size_t)NMAX * HEADS];
__device__ float g_accum[(size_t)NMAX * FTOT];   // 76.8 MB
__device__ int   g_is64;

// ---------------- helpers ----------------
__device__ __forceinline__ void atomicMaxF(float* addr, float v) {
    if (v >= 0.f) atomicMax((int*)addr, __float_as_int(v));
    else          atomicMin((unsigned int*)addr, __float_as_uint(v));
}

__device__ __forceinline__ void load_edge(const void* eidx, long E, long i,
                                          int& s, int& d) {
    if (g_is64) {
        const long long* p = (const long long*)eidx;
        s = (int)p[i];
        d = (int)p[E + i];
    } else {
        const int* p = (const int*)eidx;
        s = p[i];
        d = p[E + i];
    }
}

// ---------------- dtype detection ----------------
// If edge_index is int64, every odd int32 word (high half) of the first 64
// entries is zero (indices < 50000, nonnegative). For int32 data the odds of
// 64 consecutive odd-position values all being zero is (1/50000)^64 ~ 0.
__global__ void k_detect(const int* e32) {
    int allzero = 1;
    for (int i = 1; i < 128; i += 2)
        if (e32[i] != 0) { allzero = 0; break; }
    g_is64 = allzero;
}

// ---------------- init ----------------
__global__ void k_init(int nN) {
    long stride = (long)gridDim.x * blockDim.x;
    long i0 = (long)blockIdx.x * blockDim.x + threadIdx.x;
    long totA = (long)nN * FTOT;
    for (long j = i0; j < totA; j += stride) g_accum[j] = 0.f;
    long totS = (long)nN * HEADS;
    const float NEG_INF = __int_as_float(0xFF800000);
    for (long j = i0; j < totS; j += stride) {
        g_segmax[j] = NEG_INF;
        g_denom[j]  = 0.f;
    }
}

// ---------------- h = x @ W_pre + b_pre ----------------
// block = (64 cols, 4 row-groups), 8 rows per block, W element reused across rows
__global__ void k_pre(const float* __restrict__ x, const float* __restrict__ W,
                      const float* __restrict__ b, int nN) {
    __shared__ float xs[8][CUR];
    int col = threadIdx.x, ty = threadIdx.y;
    int tid = ty * 64 + col;
    int row0 = blockIdx.x * 8;
    for (int r = 0; r < 8; r++) {
        int rr = row0 + r;
        for (int k = tid; k < CUR; k += 256)
            xs[r][k] = (rr < nN) ? x[(size_t)rr * CUR + k] : 0.f;
    }
    __syncthreads();
    float a0 = 0.f, a1 = 0.f;
    int r0 = ty * 2, r1 = r0 + 1;
    #pragma unroll 8
    for (int k = 0; k < CUR; k++) {
        float w = W[k * HID + col];
        a0 += xs[r0][k] * w;
        a1 += xs[r1][k] * w;
    }
    float bb = b[col];
    int rr0 = row0 + r0, rr1 = row0 + r1;
    if (rr0 < nN) g_h[(size_t)rr0 * HID + col] = a0 + bb;
    if (rr1 < nN) g_h[(size_t)rr1 * HID + col] = a1 + bb;
}

// ---------------- xh = h @ W_gat ----------------
// 384 threads; each thread owns one W_gat column (64 regs), 32 rows per block
__global__ void k_gatlin(const float* __restrict__ Wg, int nN) {
    __shared__ float hs[32][HID];
    int t = threadIdx.x;         // 0..383
    int row0 = blockIdx.x * 32;
    for (int i = t; i < 32 * HID; i += 384) {
        int r = i >> 6, k = i & 63;
        int rr = row0 + r;
        hs[r][k] = (rr < nN) ? g_h[(size_t)rr * HID + k] : 0.f;
    }
    __syncthreads();
    float w[HID];
    #pragma unroll
    for (int k = 0; k < HID; k++) w[k] = Wg[k * FTOT + t];
    for (int r = 0; r < 32; r++) {
        int rr = row0 + r;
        if (rr >= nN) break;
        float v = 0.f;
        #pragma unroll
        for (int k = 0; k < HID; k++) v += hs[r][k] * w[k];
        g_xh[(size_t)rr * FTOT + t] = v;
    }
}

// ---------------- a_src / a_dst : one warp per (node, head) ----------------
__global__ void k_att(const float* __restrict__ att_s,
                      const float* __restrict__ att_d, int nN) {
    int g = blockIdx.x * (blockDim.x >> 5) + (threadIdx.x >> 5);
    int lane = threadIdx.x & 31;
    if (g >= nN * HEADS) return;
    int n = g / HEADS, hd = g % HEADS;
    const float* xr = &g_xh[(size_t)n * FTOT + hd * OUTD];
    float v0 = xr[lane], v1 = xr[lane + 32];
    float s = v0 * att_s[hd * OUTD + lane] + v1 * att_s[hd * OUTD + lane + 32];
    float d = v0 * att_d[hd * OUTD + lane] + v1 * att_d[hd * OUTD + lane + 32];
    #pragma unroll
    for (int o = 16; o > 0; o >>= 1) {
        s += __shfl_down_sync(0xffffffffu, s, o);
        d += __shfl_down_sync(0xffffffffu, d, o);
    }
    if (lane == 0) { g_asrc[g] = s; g_adst[g] = d; }
}

// ---------------- segment max over incoming edges ----------------
__global__ void k_max(const void* eidx, long E, long E2) {
    long i = (long)blockIdx.x * blockDim.x + threadIdx.x;
    if (i >= E2) return;
    int s, d;
    if (i < E) load_edge(eidx, E, i, s, d);
    else       s = d = (int)(i - E);
    #pragma unroll
    for (int hd = 0; hd < HEADS; hd++) {
        float a = g_asrc[s * HEADS + hd] + g_adst[d * HEADS + hd];
        a = (a > 0.f) ? a : 0.2f * a;
        atomicMaxF(&g_segmax[d * HEADS + hd], a);
    }
}

// ---------------- scatter: denom += ex ; accum[dst] += ex * xh[src] --------
// one warp per edge
__global__ void k_scatter(const void* eidx, long E, long E2) {
    long wid = (long)blockIdx.x * (blockDim.x >> 5) + (threadIdx.x >> 5);
    if (wid >= E2) return;
    int lane = threadIdx.x & 31;
    int s, d;
    if (wid < E) load_edge(eidx, E, wid, s, d);
    else         s = d = (int)(wid - E);
    float ex = 0.f;
    if (lane < HEADS) {
        float a = g_asrc[s * HEADS + lane] + g_adst[d * HEADS + lane];
        a = (a > 0.f) ? a : 0.2f * a;
        ex = __expf(a - g_segmax[d * HEADS + lane]);
        atomicAdd(&g_denom[d * HEADS + lane], ex);
    }
    __syncwarp();
    const float* xs = &g_xh[(size_t)s * FTOT];
    float* ac = &g_accum[(size_t)d * FTOT];
    #pragma unroll
    for (int j = 0; j < 12; j++) {
        int f = j * 32 + lane;
        float w = __shfl_sync(0xffffffffu, ex, f >> 6);
        atomicAdd(&ac[f], w * xs[f]);
    }
}

// ---------------- finalize + out = [h, h1] @ W_lin + b_lin ----------------
__global__ void k_final(const float* __restrict__ bg, const float* __restrict__ Wl,
                        const float* __restrict__ bl, float* __restrict__ out,
                        int nN) {
    __shared__ float cat[8][CATD];
    int col = threadIdx.x, ty = threadIdx.y;
    int tid = ty * 64 + col;
    int row0 = blockIdx.x * 8;
    for (int i = tid; i < 8 * CATD; i += 256) {
        int r = i / CATD, f = i % CATD;
        int rr = row0 + r;
        float v = 0.f;
        if (rr < nN) {
            if (f < HID) {
                v = g_h[(size_t)rr * HID + f];
            } else {
                int ff = f - HID;
                float t = g_accum[(size_t)rr * FTOT + ff] /
                          g_denom[rr * HEADS + (ff >> 6)] + bg[ff];
                v = (t > 0.f) ? t : 0.01f * t;
            }
        }
        cat[r][f] = v;
    }
    __syncthreads();
    float a0 = 0.f, a1 = 0.f;
    int r0 = ty * 2, r1 = r0 + 1;
    #pragma unroll 8
    for (int k = 0; k < CATD; k++) {
        float w = Wl[k * OUTD + col];
        a0 += cat[r0][k] * w;
        a1 += cat[r1][k] * w;
    }
    float bb = bl[col];
    int rr0 = row0 + r0, rr1 = row0 + r1;
    if (rr0 < nN) out[(size_t)rr0 * OUTD + col] = a0 + bb;
    if (rr1 < nN) out[(size_t)rr1 * OUTD + col] = a1 + bb;
}

// ---------------- launch ----------------
extern "C" void kernel_launch(void* const* d_in, const int* in_sizes, int n_in,
                              void* d_out, int out_size) {
    const float* x    = (const float*)d_in[0];
    const void*  eidx = d_in[1];
    // d_in[2] = edge_weight (unused by the reference forward)
    const float* Wpre = (const float*)d_in[3];
    const float* bpre = (const float*)d_in[4];
    const float* Wgat = (const float*)d_in[5];
    const float* atts = (const float*)d_in[6];
    const float* attd = (const float*)d_in[7];
    const float* bgat = (const float*)d_in[8];
    const float* Wlin = (const float*)d_in[9];
    const float* blin = (const float*)d_in[10];
    float* out = (float*)d_out;

    int  nN = in_sizes[0] / CUR;
    long E  = (long)in_sizes[1] / 2;
    long E2 = E + nN;

    k_detect<<<1, 1>>>((const int*)eidx);
    k_init<<<2048, 256>>>(nN);
    k_pre<<<(nN + 7) / 8, dim3(64, 4)>>>(x, Wpre, bpre, nN);
    k_gatlin<<<(nN + 31) / 32, 384>>>(Wgat, nN);
    k_att<<<(nN * HEADS + 7) / 8, 256>>>(atts, attd, nN);
    k_max<<<(int)((E2 + 255) / 256), 256>>>(eidx, E, E2);
    k_scatter<<<(int)((E2 + 7) / 8), 256>>>(eidx, E, E2);
    k_final<<<(nN + 7) / 8, dim3(64, 4)>>>(bgat, Wlin, blin, out, nN);
}

// round 2
// speedup vs baseline: 1.5683x; 1.5683x over previous
#include <cuda_runtime.h>
#include <cuda_bf16.h>

// Problem constants
#define CUR   512
#define HID   64
#define OUTD  64
#define HEADS 6
#define FTOT  (HEADS*OUTD)   // 384
#define CATD  (HID + FTOT)   // 448
#define NMAX  50000
#define EMAX  860000         // E + N self-loops

// ---------------- device scratch (no allocations allowed) ----------------
__device__ float g_h[(size_t)NMAX * HID];        // 12.8 MB
__device__ float g_xh[(size_t)NMAX * FTOT];      // 76.8 MB
__device__ float g_asrc[(size_t)NMAX * HEADS];
__device__ float g_adst[(size_t)NMAX * HEADS];
__device__ float g_h1[(size_t)NMAX * FTOT];      // 76.8 MB (GAT output)
__device__ int   g_deg[NMAX];
__device__ int   g_cnt[NMAX];
__device__ int   g_off[NMAX + 1];
__device__ int   g_csrc[EMAX];
__device__ int   g_is64;

// ---------------- helpers ----------------
__device__ __forceinline__ void load_edge(const void* eidx, long E, long i,
                                          int& s, int& d) {
    if (g_is64) {
        const long long* p = (const long long*)eidx;
        s = (int)p[i];
        d = (int)p[E + i];
    } else {
        const int* p = (const int*)eidx;
        s = p[i];
        d = p[E + i];
    }
}

// ---------------- dtype detection ----------------
// int64 indices < 50000 => all high words zero over first 64 entries.
__global__ void k_detect(const int* e32) {
    int allzero = 1;
    for (int i = 1; i < 128; i += 2)
        if (e32[i] != 0) { allzero = 0; break; }
    g_is64 = allzero;
}

// ---------------- zero degree counters ----------------
__global__ void k_zero(int nN) {
    int i = blockIdx.x * blockDim.x + threadIdx.x;
    if (i < nN) { g_deg[i] = 0; g_cnt[i] = 0; }
}

// ---------------- histogram of dst (incl. self loops) ----------------
__global__ void k_hist(const void* eidx, long E, long E2) {
    long i = (long)blockIdx.x * blockDim.x + threadIdx.x;
    if (i >= E2) return;
    int s, d;
    if (i < E) load_edge(eidx, E, i, s, d);
    else       d = (int)(i - E);
    atomicAdd(&g_deg[d], 1);
}

// ---------------- exclusive scan over g_deg (single block) ----------------
__global__ void k_scan(int nN) {
    __shared__ int part[1024];
    int t = threadIdx.x;
    int chunk = (nN + 1023) / 1024;
    int lo = t * chunk;
    int hi = lo + chunk; if (hi > nN) hi = nN; if (lo > nN) lo = nN;
    int s = 0;
    for (int i = lo; i < hi; i++) s += g_deg[i];
    part[t] = s;
    __syncthreads();
    for (int o = 1; o < 1024; o <<= 1) {
        int v = 0;
        if (t >= o) v = part[t - o];
        __syncthreads();
        if (t >= o) part[t] += v;
        __syncthreads();
    }
    int run = (t > 0) ? part[t - 1] : 0;
    for (int i = lo; i < hi; i++) {
        g_off[i] = run;
        run += g_deg[i];
    }
    if (t == 1023) g_off[nN] = part[1023];
}

// ---------------- CSR fill ----------------
__global__ void k_fill(const void* eidx, long E, long E2) {
    long i = (long)blockIdx.x * blockDim.x + threadIdx.x;
    if (i >= E2) return;
    int s, d;
    if (i < E) load_edge(eidx, E, i, s, d);
    else       s = d = (int)(i - E);
    int pos = g_off[d] + atomicAdd(&g_cnt[d], 1);
    g_csrc[pos] = s;
}

// ---------------- h = x @ W_pre + b_pre ----------------
__global__ void k_pre(const float* __restrict__ x, const float* __restrict__ W,
                      const float* __restrict__ b, int nN) {
    __shared__ float xs[8][CUR];
    int col = threadIdx.x, ty = threadIdx.y;
    int tid = ty * 64 + col;
    int row0 = blockIdx.x * 8;
    for (int r = 0; r < 8; r++) {
        int rr = row0 + r;
        for (int k = tid; k < CUR; k += 256)
            xs[r][k] = (rr < nN) ? x[(size_t)rr * CUR + k] : 0.f;
    }
    __syncthreads();
    float a0 = 0.f, a1 = 0.f;
    int r0 = ty * 2, r1 = r0 + 1;
    #pragma unroll 8
    for (int k = 0; k < CUR; k++) {
        float w = W[k * HID + col];
        a0 += xs[r0][k] * w;
        a1 += xs[r1][k] * w;
    }
    float bb = b[col];
    int rr0 = row0 + r0, rr1 = row0 + r1;
    if (rr0 < nN) g_h[(size_t)rr0 * HID + col] = a0 + bb;
    if (rr1 < nN) g_h[(size_t)rr1 * HID + col] = a1 + bb;
}

// ---------------- xh = h @ W_gat ----------------
__global__ void __launch_bounds__(384, 2)
k_gatlin(const float* __restrict__ Wg, int nN) {
    __shared__ float hs[32][HID];
    int t = threadIdx.x;         // 0..383
    int row0 = blockIdx.x * 32;
    for (int i = t; i < 32 * HID; i += 384) {
        int r = i >> 6, k = i & 63;
        int rr = row0 + r;
        hs[r][k] = (rr < nN) ? g_h[(size_t)rr * HID + k] : 0.f;
    }
    __syncthreads();
    float w[HID];
    #pragma unroll
    for (int k = 0; k < HID; k++) w[k] = Wg[k * FTOT + t];
    for (int r = 0; r < 32; r++) {
        int rr = row0 + r;
        if (rr >= nN) break;
        float v = 0.f;
        #pragma unroll
        for (int k = 0; k < HID; k++) v += hs[r][k] * w[k];
        g_xh[(size_t)rr * FTOT + t] = v;
    }
}

// ---------------- a_src / a_dst : one warp per (node, head) ----------------
__global__ void k_att(const float* __restrict__ att_s,
                      const float* __restrict__ att_d, int nN) {
    int g = blockIdx.x * (blockDim.x >> 5) + (threadIdx.x >> 5);
    int lane = threadIdx.x & 31;
    if (g >= nN * HEADS) return;
    int n = g / HEADS, hd = g % HEADS;
    const float* xr = &g_xh[(size_t)n * FTOT + hd * OUTD];
    float v0 = xr[lane], v1 = xr[lane + 32];
    float s = v0 * att_s[hd * OUTD + lane] + v1 * att_s[hd * OUTD + lane + 32];
    float d = v0 * att_d[hd * OUTD + lane] + v1 * att_d[hd * OUTD + lane + 32];
    #pragma unroll
    for (int o = 16; o > 0; o >>= 1) {
        s += __shfl_down_sync(0xffffffffu, s, o);
        d += __shfl_down_sync(0xffffffffu, d, o);
    }
    if (lane == 0) { g_asrc[g] = s; g_adst[g] = d; }
}

// ---------------- CSR gather: softmax + weighted sum, atomic-free ---------
// one warp per dst node; output = leakyrelu(sum/denom + b_gat, 0.01)
#define GW 8   // warps per block
__global__ void k_gather(const float* __restrict__ bg, int nN) {
    __shared__ float exs[GW][32][HEADS];
    int w = threadIdx.x >> 5;
    int n = blockIdx.x * GW + w;
    if (n >= nN) return;
    int lane = threadIdx.x & 31;
    int lo = g_off[n], hi = g_off[n + 1];

    // broadcast a_dst[n][0..5] to all lanes
    float adv = (lane < HEADS) ? g_adst[n * HEADS + lane] : 0.f;
    float adn[HEADS];
    #pragma unroll
    for (int h = 0; h < HEADS; h++) adn[h] = __shfl_sync(0xffffffffu, adv, h);

    // pass A: per-head max over incoming edges
    float mx[HEADS];
    #pragma unroll
    for (int h = 0; h < HEADS; h++) mx[h] = -1e30f;
    for (int j = lo + lane; j < hi; j += 32) {
        int s = g_csrc[j];
        #pragma unroll
        for (int h = 0; h < HEADS; h++) {
            float a = g_asrc[s * HEADS + h] + adn[h];
            a = (a > 0.f) ? a : 0.2f * a;
            mx[h] = fmaxf(mx[h], a);
        }
    }
    #pragma unroll
    for (int h = 0; h < HEADS; h++)
        #pragma unroll
        for (int o = 16; o > 0; o >>= 1)
            mx[h] = fmaxf(mx[h], __shfl_xor_sync(0xffffffffu, mx[h], o));

    // pass B: accumulate ex * xh[src] and denom, chunked by 32 edges
    float acc[12];
    #pragma unroll
    for (int q = 0; q < 12; q++) acc[q] = 0.f;
    float den[HEADS];
    #pragma unroll
    for (int h = 0; h < HEADS; h++) den[h] = 0.f;

    for (int base = lo; base < hi; base += 32) {
        int j = base + lane;
        int s = -1;
        if (j < hi) {
            s = g_csrc[j];
            #pragma unroll
            for (int h = 0; h < HEADS; h++) {
                float a = g_asrc[s * HEADS + h] + adn[h];
                a = (a > 0.f) ? a : 0.2f * a;
                float ex = __expf(a - mx[h]);
                den[h] += ex;
                exs[w][lane][h] = ex;
            }
        }
        __syncwarp();
        int cnt = hi - base; if (cnt > 32) cnt = 32;
        for (int e = 0; e < cnt; e++) {
            int se = __shfl_sync(0xffffffffu, s, e);
            const float4* xs = (const float4*)&g_xh[(size_t)se * FTOT];
            #pragma unroll
            for (int q = 0; q < 3; q++) {
                int fq = q * 32 + lane;          // float4 index
                int h = 2 * q + (lane >> 4);     // head of these 4 floats
                float ex = exs[w][e][h];
                float4 v = xs[fq];
                acc[q * 4 + 0] += ex * v.x;
                acc[q * 4 + 1] += ex * v.y;
                acc[q * 4 + 2] += ex * v.z;
                acc[q * 4 + 3] += ex * v.w;
            }
        }
        __syncwarp();
    }

    // reduce denom across lanes
    #pragma unroll
    for (int h = 0; h < HEADS; h++)
        #pragma unroll
        for (int o = 16; o > 0; o >>= 1)
            den[h] += __shfl_xor_sync(0xffffffffu, den[h], o);

    // normalize + bias + leaky_relu(0.01), write h1
    float4* outp = (float4*)&g_h1[(size_t)n * FTOT];
    #pragma unroll
    for (int q = 0; q < 3; q++) {
        int fq = q * 32 + lane;
        int h = 2 * q + (lane >> 4);
        float inv = 1.f / den[h];
        int f0 = fq * 4;
        float4 r;
        float t;
        t = acc[q * 4 + 0] * inv + bg[f0 + 0]; r.x = (t > 0.f) ? t : 0.01f * t;
        t = acc[q * 4 + 1] * inv + bg[f0 + 1]; r.y = (t > 0.f) ? t : 0.01f * t;
        t = acc[q * 4 + 2] * inv + bg[f0 + 2]; r.z = (t > 0.f) ? t : 0.01f * t;
        t = acc[q * 4 + 3] * inv + bg[f0 + 3]; r.w = (t > 0.f) ? t : 0.01f * t;
        outp[fq] = r;
    }
}

// ---------------- out = [h, h1] @ W_lin + b_lin ----------------
__global__ void k_final(const float* __restrict__ Wl, const float* __restrict__ bl,
                        float* __restrict__ out, int nN) {
    __shared__ float cat[8][CATD];
    int col = threadIdx.x, ty = threadIdx.y;
    int tid = ty * 64 + col;
    int row0 = blockIdx.x * 8;
    for (int i = tid; i < 8 * CATD; i += 256) {
        int r = i / CATD, f = i % CATD;
        int rr = row0 + r;
        float v = 0.f;
        if (rr < nN) {
            if (f < HID) v = g_h[(size_t)rr * HID + f];
            else         v = g_h1[(size_t)rr * FTOT + (f - HID)];
        }
        cat[r][f] = v;
    }
    __syncthreads();
    float a0 = 0.f, a1 = 0.f;
    int r0 = ty * 2, r1 = r0 + 1;
    #pragma unroll 8
    for (int k = 0; k < CATD; k++) {
        float w = Wl[k * OUTD + col];
        a0 += cat[r0][k] * w;
        a1 += cat[r1][k] * w;
    }
    float bb = bl[col];
    int rr0 = row0 + r0, rr1 = row0 + r1;
    if (rr0 < nN) out[(size_t)rr0 * OUTD + col] = a0 + bb;
    if (rr1 < nN) out[(size_t)rr1 * OUTD + col] = a1 + bb;
}

// ---------------- launch ----------------
extern "C" void kernel_launch(void* const* d_in, const int* in_sizes, int n_in,
                              void* d_out, int out_size) {
    const float* x    = (const float*)d_in[0];
    const void*  eidx = d_in[1];
    // d_in[2] = edge_weight (unused by the reference forward)
    const float* Wpre = (const float*)d_in[3];
    const float* bpre = (const float*)d_in[4];
    const float* Wgat = (const float*)d_in[5];
    const float* atts = (const float*)d_in[6];
    const float* attd = (const float*)d_in[7];
    const float* bgat = (const float*)d_in[8];
    const float* Wlin = (const float*)d_in[9];
    const float* blin = (const float*)d_in[10];
    float* out = (float*)d_out;

    int  nN = in_sizes[0] / CUR;
    long E  = (long)in_sizes[1] / 2;
    long E2 = E + nN;

    k_detect<<<1, 1>>>((const int*)eidx);
    k_zero<<<(nN + 255) / 256, 256>>>(nN);
    k_pre<<<(nN + 7) / 8, dim3(64, 4)>>>(x, Wpre, bpre, nN);
    k_gatlin<<<(nN + 31) / 32, 384>>>(Wgat, nN);
    k_att<<<(nN * HEADS + 7) / 8, 256>>>(atts, attd, nN);
    k_hist<<<(int)((E2 + 255) / 256), 256>>>(eidx, E, E2);
    k_scan<<<1, 1024>>>(nN);
    k_fill<<<(int)((E2 + 255) / 256), 256>>>(eidx, E, E2);
    k_gather<<<(nN + GW - 1) / GW, GW * 32>>>(bgat, nN);
    k_final<<<(nN + 7) / 8, dim3(64, 4)>>>(Wlin, blin, out, nN);
}

// round 8
// speedup vs baseline: 1.8532x; 1.1816x over previous
#include <cuda_runtime.h>
#include <cuda_bf16.h>

// Problem constants
#define CUR   512
#define HID   64
#define OUTD  64
#define HEADS 6
#define FTOT  (HEADS*OUTD)   // 384
#define CATD  (HID + FTOT)   // 448
#define NMAX  50000
#define EMAX  860000

// ---------------- device scratch ----------------
__device__ float g_h[(size_t)NMAX * HID];        // 12.8 MB (L2 resident)
__device__ float g_acc[(size_t)NMAX * FTOT];     // gathered, normalized
__device__ float g_h1[(size_t)NMAX * FTOT];      // GAT output
__device__ float g_asrc[(size_t)NMAX * HEADS];
__device__ float g_adst[(size_t)NMAX * HEADS];
__device__ float g_ws[HID * HEADS];              // W_gat_h @ att_src_h
__device__ float g_wd[HID * HEADS];
__device__ int   g_deg[NMAX];
__device__ int   g_cnt[NMAX];
__device__ int   g_off[NMAX + 1];
__device__ int   g_csrc[EMAX];
__device__ int   g_is64;

// ---------------- helpers ----------------
__device__ __forceinline__ void load_edge(const void* eidx, long E, long i,
                                          int& s, int& d) {
    if (g_is64) {
        const long long* p = (const long long*)eidx;
        s = (int)p[i];
        d = (int)p[E + i];
    } else {
        const int* p = (const int*)eidx;
        s = p[i];
        d = p[E + i];
    }
}

// int64 indices < 50000 => all high words zero over first 64 entries.
__global__ void k_detect(const int* e32) {
    int allzero = 1;
    for (int i = 1; i < 128; i += 2)
        if (e32[i] != 0) { allzero = 0; break; }
    g_is64 = allzero;
}

__global__ void k_zero(int nN) {
    int i = blockIdx.x * blockDim.x + threadIdx.x;
    if (i < nN) { g_deg[i] = 0; g_cnt[i] = 0; }
}

// ws[k][h] = sum_c W_gat[k, h*64+c] * att_src[h][c]   (and wd with att_dst)
__global__ void k_wsd(const float* __restrict__ Wg,
                      const float* __restrict__ as_,
                      const float* __restrict__ ad_) {
    int t = threadIdx.x;            // 0..383
    int h = t >> 6, k = t & 63;
    float s = 0.f, d = 0.f;
    #pragma unroll 8
    for (int c = 0; c < OUTD; c++) {
        float wv = Wg[k * FTOT + h * OUTD + c];
        s += wv * as_[h * OUTD + c];
        d += wv * ad_[h * OUTD + c];
    }
    g_ws[k * HEADS + h] = s;
    g_wd[k * HEADS + h] = d;
}

// ---------------- histogram of dst ----------------
__global__ void k_hist(const void* eidx, long E, long E2) {
    long i = (long)blockIdx.x * blockDim.x + threadIdx.x;
    if (i >= E2) return;
    int d;
    if (i < E) {
        if (g_is64) d = (int)((const long long*)eidx)[E + i];
        else        d = ((const int*)eidx)[E + i];
    } else d = (int)(i - E);
    atomicAdd(&g_deg[d], 1);
}

// ---------------- exclusive scan (single block) ----------------
__global__ void k_scan(int nN) {
    __shared__ int part[1024];
    int t = threadIdx.x;
    int chunk = (nN + 1023) / 1024;
    int lo = t * chunk;
    int hi = lo + chunk; if (hi > nN) hi = nN; if (lo > nN) lo = nN;
    int s = 0;
    for (int i = lo; i < hi; i++) s += g_deg[i];
    part[t] = s;
    __syncthreads();
    for (int o = 1; o < 1024; o <<= 1) {
        int v = 0;
        if (t >= o) v = part[t - o];
        __syncthreads();
        if (t >= o) part[t] += v;
        __syncthreads();
    }
    int run = (t > 0) ? part[t - 1] : 0;
    for (int i = lo; i < hi; i++) { g_off[i] = run; run += g_deg[i]; }
    if (t == 1023) g_off[nN] = part[1023];
}

__global__ void k_fill(const void* eidx, long E, long E2) {
    long i = (long)blockIdx.x * blockDim.x + threadIdx.x;
    if (i >= E2) return;
    int s, d;
    if (i < E) load_edge(eidx, E, i, s, d);
    else       s = d = (int)(i - E);
    int pos = g_off[d] + atomicAdd(&g_cnt[d], 1);
    g_csrc[pos] = s;
}

// ---------------- h = x @ W_pre + b_pre  (16 rows/block, 4 rows/thread) ----
__global__ void __launch_bounds__(256, 2)
k_pre(const float* __restrict__ x, const float* __restrict__ W,
      const float* __restrict__ b, int nN) {
    __shared__ float xs[16][CUR];
    int col = threadIdx.x, ty = threadIdx.y;
    int tid = ty * 64 + col;
    int row0 = blockIdx.x * 16;
    float4* xsv = (float4*)&xs[0][0];
    const int VROW = CUR / 4;  // 128
    for (int i = tid; i < 16 * VROW; i += 256) {
        int r = i / VROW, q = i % VROW;
        int rr = row0 + r;
        float4 v = make_float4(0.f, 0.f, 0.f, 0.f);
        if (rr < nN) v = ((const float4*)(x + (size_t)rr * CUR))[q];
        xsv[i] = v;
    }
    __syncthreads();
    float a0 = 0.f, a1 = 0.f, a2 = 0.f, a3 = 0.f;
    int r0 = ty * 4;
    #pragma unroll 4
    for (int k = 0; k < CUR; k += 4) {
        float w0 = W[(k + 0) * HID + col];
        float w1 = W[(k + 1) * HID + col];
        float w2 = W[(k + 2) * HID + col];
        float w3 = W[(k + 3) * HID + col];
        float4 v0 = *(float4*)&xs[r0 + 0][k];
        float4 v1 = *(float4*)&xs[r0 + 1][k];
        float4 v2 = *(float4*)&xs[r0 + 2][k];
        float4 v3 = *(float4*)&xs[r0 + 3][k];
        a0 += v0.x * w0 + v0.y * w1 + v0.z * w2 + v0.w * w3;
        a1 += v1.x * w0 + v1.y * w1 + v1.z * w2 + v1.w * w3;
        a2 += v2.x * w0 + v2.y * w1 + v2.z * w2 + v2.w * w3;
        a3 += v3.x * w0 + v3.y * w1 + v3.z * w2 + v3.w * w3;
    }
    float bb = b[col];
    int rr = row0 + r0;
    if (rr + 0 < nN) g_h[(size_t)(rr + 0) * HID + col] = a0 + bb;
    if (rr + 1 < nN) g_h[(size_t)(rr + 1) * HID + col] = a1 + bb;
    if (rr + 2 < nN) g_h[(size_t)(rr + 2) * HID + col] = a2 + bb;
    if (rr + 3 < nN) g_h[(size_t)(rr + 3) * HID + col] = a3 + bb;
}

// ---------------- a_src / a_dst from h directly: warp per node ------------
__global__ void k_att2(int nN) {
    int n = blockIdx.x * (blockDim.x >> 5) + (threadIdx.x >> 5);
    if (n >= nN) return;
    int lane = threadIdx.x & 31;
    float h0 = g_h[(size_t)n * HID + lane];
    float h1v = g_h[(size_t)n * HID + 32 + lane];
    float sv[HEADS], dv[HEADS];
    #pragma unroll
    for (int h = 0; h < HEADS; h++) {
        sv[h] = h0 * g_ws[lane * HEADS + h] + h1v * g_ws[(lane + 32) * HEADS + h];
        dv[h] = h0 * g_wd[lane * HEADS + h] + h1v * g_wd[(lane + 32) * HEADS + h];
    }
    #pragma unroll
    for (int o = 16; o > 0; o >>= 1) {
        #pragma unroll
        for (int h = 0; h < HEADS; h++) {
            sv[h] += __shfl_xor_sync(0xffffffffu, sv[h], o);
            dv[h] += __shfl_xor_sync(0xffffffffu, dv[h], o);
        }
    }
    if (lane == 0) {
        #pragma unroll
        for (int h = 0; h < HEADS; h++) {
            g_asrc[n * HEADS + h] = sv[h];
            g_adst[n * HEADS + h] = dv[h];
        }
    }
}

// ---------------- CSR gather of h[src]: softmax-weighted, atomic-free -----
// one warp per dst node; writes normalized per-head accumulators (384/node)
#define GW 8
__global__ void k_gather(int nN) {
    __shared__ float exs[GW][32][HEADS];
    int w = threadIdx.x >> 5;
    int n = blockIdx.x * GW + w;
    if (n >= nN) return;
    int lane = threadIdx.x & 31;
    int lo = g_off[n], hi = g_off[n + 1];

    float adv = (lane < HEADS) ? g_adst[n * HEADS + lane] : 0.f;
    float adn[HEADS];
    #pragma unroll
    for (int h = 0; h < HEADS; h++) adn[h] = __shfl_sync(0xffffffffu, adv, h);

    // pass A: per-head max
    float mx[HEADS];
    #pragma unroll
    for (int h = 0; h < HEADS; h++) mx[h] = -1e30f;
    for (int j = lo + lane; j < hi; j += 32) {
        int s = g_csrc[j];
        const float2* ap = (const float2*)&g_asrc[s * HEADS];
        float2 a01 = ap[0], a23 = ap[1], a45 = ap[2];
        float av[HEADS] = {a01.x, a01.y, a23.x, a23.y, a45.x, a45.y};
        #pragma unroll
        for (int h = 0; h < HEADS; h++) {
            float a = av[h] + adn[h];
            a = (a > 0.f) ? a : 0.2f * a;
            mx[h] = fmaxf(mx[h], a);
        }
    }
    #pragma unroll
    for (int h = 0; h < HEADS; h++)
        #pragma unroll
        for (int o = 16; o > 0; o >>= 1)
            mx[h] = fmaxf(mx[h], __shfl_xor_sync(0xffffffffu, mx[h], o));

    // pass B: acc[h][2] over dims (2*lane, 2*lane+1); denom per head
    float acc[2 * HEADS];
    #pragma unroll
    for (int q = 0; q < 2 * HEADS; q++) acc[q] = 0.f;
    float den[HEADS];
    #pragma unroll
    for (int h = 0; h < HEADS; h++) den[h] = 0.f;

    for (int base = lo; base < hi; base += 32) {
        int j = base + lane;
        int s = 0;
        if (j < hi) {
            s = g_csrc[j];
            const float2* ap = (const float2*)&g_asrc[s * HEADS];
            float2 a01 = ap[0], a23 = ap[1], a45 = ap[2];
            float av[HEADS] = {a01.x, a01.y, a23.x, a23.y, a45.x, a45.y};
            #pragma unroll
            for (int h = 0; h < HEADS; h++) {
                float a = av[h] + adn[h];
                a = (a > 0.f) ? a : 0.2f * a;
                float ex = __expf(a - mx[h]);
                den[h] += ex;
                exs[w][lane][h] = ex;
            }
        }
        __syncwarp();
        int cnt = hi - base; if (cnt > 32) cnt = 32;
        for (int e = 0; e < cnt; e++) {
            int se = __shfl_sync(0xffffffffu, s, e);
            float2 hv = ((const float2*)(g_h + (size_t)se * HID))[lane];
            #pragma unroll
            for (int h = 0; h < HEADS; h++) {
                float ex = exs[w][e][h];
                acc[2 * h + 0] += ex * hv.x;
                acc[2 * h + 1] += ex * hv.y;
            }
        }
        __syncwarp();
    }

    #pragma unroll
    for (int h = 0; h < HEADS; h++)
        #pragma unroll
        for (int o = 16; o > 0; o >>= 1)
            den[h] += __shfl_xor_sync(0xffffffffu, den[h], o);

    #pragma unroll
    for (int h = 0; h < HEADS; h++) {
        float inv = 1.f / den[h];
        float2 st;
        st.x = acc[2 * h + 0] * inv;
        st.y = acc[2 * h + 1] * inv;
        ((float2*)(g_acc + (size_t)n * FTOT + h * OUTD))[lane] = st;
    }
}

// ---------------- h1 = leakyrelu(per-head acc @ W_gat + b_gat, 0.01) ------
__global__ void __launch_bounds__(384, 2)
k_h1(const float* __restrict__ Wg, const float* __restrict__ bg, int nN) {
    __shared__ float as[16][FTOT];
    int t = threadIdx.x;
    int row0 = blockIdx.x * 16;
    float4* asv = (float4*)&as[0][0];
    const int VROW = FTOT / 4;  // 96
    for (int i = t; i < 16 * VROW; i += 384) {
        int r = i / VROW, q = i % VROW;
        int rr = row0 + r;
        float4 v = make_float4(0.f, 0.f, 0.f, 0.f);
        if (rr < nN) v = ((const float4*)(g_acc + (size_t)rr * FTOT))[q];
        asv[i] = v;
    }
    __syncthreads();
    float wreg[HID];
    #pragma unroll
    for (int k = 0; k < HID; k++) wreg[k] = Wg[k * FTOT + t];
    int kb = (t >> 6) * OUTD;   // head offset into acc row
    float bb = bg[t];
    for (int r = 0; r < 16; r++) {
        int rr = row0 + r;
        if (rr >= nN) break;
        float v = 0.f;
        #pragma unroll
        for (int k = 0; k < HID; k += 4) {
            float4 hv = *(float4*)&as[r][kb + k];
            v += hv.x * wreg[k] + hv.y * wreg[k + 1] + hv.z * wreg[k + 2] + hv.w * wreg[k + 3];
        }
        v += bb;
        g_h1[(size_t)rr * FTOT + t] = (v > 0.f) ? v : 0.01f * v;
    }
}

// ---------------- out = [h, h1] @ W_lin + b_lin ----------------
__global__ void __launch_bounds__(256, 2)
k_final(const float* __restrict__ Wl, const float* __restrict__ bl,
        float* __restrict__ out, int nN) {
    __shared__ float cat[16][CATD];
    int col = threadIdx.x, ty = threadIdx.y;
    int tid = ty * 64 + col;
    int row0 = blockIdx.x * 16;
    float4* catv = (float4*)&cat[0][0];
    const int VROW = CATD / 4;  // 112
    for (int i = tid; i < 16 * VROW; i += 256) {
        int r = i / VROW, q = i % VROW;
        int rr = row0 + r;
        float4 v = make_float4(0.f, 0.f, 0.f, 0.f);
        if (rr < nN) {
            if (q < HID / 4) v = ((const float4*)(g_h + (size_t)rr * HID))[q];
            else             v = ((const float4*)(g_h1 + (size_t)rr * FTOT))[q - HID / 4];
        }
        catv[i] = v;
    }
    __syncthreads();
    float a0 = 0.f, a1 = 0.f, a2 = 0.f, a3 = 0.f;
    int r0 = ty * 4;
    #pragma unroll 4
    for (int k = 0; k < CATD; k += 4) {
        float w0 = Wl[(k + 0) * OUTD + col];
        float w1 = Wl[(k + 1) * OUTD + col];
        float w2 = Wl[(k + 2) * OUTD + col];
        float w3 = Wl[(k + 3) * OUTD + col];
        float4 v0 = *(float4*)&cat[r0 + 0][k];
        float4 v1 = *(float4*)&cat[r0 + 1][k];
        float4 v2 = *(float4*)&cat[r0 + 2][k];
        float4 v3 = *(float4*)&cat[r0 + 3][k];
        a0 += v0.x * w0 + v0.y * w1 + v0.z * w2 + v0.w * w3;
        a1 += v1.x * w0 + v1.y * w1 + v1.z * w2 + v1.w * w3;
        a2 += v2.x * w0 + v2.y * w1 + v2.z * w2 + v2.w * w3;
        a3 += v3.x * w0 + v3.y * w1 + v3.z * w2 + v3.w * w3;
    }
    float bb = bl[col];
    int rr = row0 + r0;
    if (rr + 0 < nN) out[(size_t)(rr + 0) * OUTD + col] = a0 + bb;
    if (rr + 1 < nN) out[(size_t)(rr + 1) * OUTD + col] = a1 + bb;
    if (rr + 2 < nN) out[(size_t)(rr + 2) * OUTD + col] = a2 + bb;
    if (rr + 3 < nN) out[(size_t)(rr + 3) * OUTD + col] = a3 + bb;
}

// ---------------- launch ----------------
extern "C" void kernel_launch(void* const* d_in, const int* in_sizes, int n_in,
                              void* d_out, int out_size) {
    const float* x    = (const float*)d_in[0];
    const void*  eidx = d_in[1];
    const float* Wpre = (const float*)d_in[3];
    const float* bpre = (const float*)d_in[4];
    const float* Wgat = (const float*)d_in[5];
    const float* atts = (const float*)d_in[6];
    const float* attd = (const float*)d_in[7];
    const float* bgat = (const float*)d_in[8];
    const float* Wlin = (const float*)d_in[9];
    const float* blin = (const float*)d_in[10];
    float* out = (float*)d_out;

    int  nN = in_sizes[0] / CUR;
    long E  = (long)in_sizes[1] / 2;
    long E2 = E + nN;

    k_detect<<<1, 1>>>((const int*)eidx);
    k_zero<<<(nN + 255) / 256, 256>>>(nN);
    k_wsd<<<1, 384>>>(Wgat, atts, attd);
    k_pre<<<(nN + 15) / 16, dim3(64, 4)>>>(x, Wpre, bpre, nN);
    k_att2<<<(nN + 7) / 8, 256>>>(nN);
    k_hist<<<(int)((E2 + 255) / 256), 256>>>(eidx, E, E2);
    k_scan<<<1, 1024>>>(nN);
    k_fill<<<(int)((E2 + 255) / 256), 256>>>(eidx, E, E2);
    k_gather<<<(nN + GW - 1) / GW, GW * 32>>>(nN);
    k_h1<<<(nN + 15) / 16, 384>>>(Wgat, bgat, nN);
    k_final<<<(nN + 15) / 16, dim3(64, 4)>>>(Wlin, blin, out, nN);
}